// round 10
// baseline (speedup 1.0000x reference)
#include <cuda_runtime.h>
#include <cuda_bf16.h>
#include <math.h>

// Problem constants
#define B    256
#define S    196
#define D    1024
#define P    512
#define L    8
#define TOPK 4

// k-split for sim GEMM
#define KSPLIT 16
#define KCH    (D / KSPLIT)   // 64
#define PITCH  132            // float4-aligned, conflict-free compute reads

// Scratch (no cudaMalloc allowed)
__device__ float g_qpart[4][B * D];        // mean partials over S quarters
__device__ float g_qn[B * D];              // normalized query
__device__ float g_keyn[P * D];            // normalized keys
__device__ float g_simpart[KSPLIT][B * P]; // partial sims
__device__ int   g_idx[TOPK * B];          // selected prompt indices

// ---------------------------------------------------------------------------
// f32x2 packed-FMA helpers (two independent IEEE fp32 FMAs per instr)
// ---------------------------------------------------------------------------
__device__ __forceinline__ unsigned long long fma2(unsigned long long a,
                                                   unsigned long long b,
                                                   unsigned long long c) {
    unsigned long long d;
    asm("fma.rn.f32x2 %0, %1, %2, %3;" : "=l"(d) : "l"(a), "l"(b), "l"(c));
    return d;
}
__device__ __forceinline__ unsigned long long pack2(float x, float y) {
    unsigned long long d;
    asm("mov.b64 %0, {%1, %2};" : "=l"(d) : "f"(x), "f"(y));
    return d;
}
__device__ __forceinline__ void unpack2(unsigned long long v, float& x, float& y) {
    asm("mov.b64 {%0, %1}, %2;" : "=f"(x), "=f"(y) : "l"(v));
}

// ---------------------------------------------------------------------------
// K1: mean partials.  grid(B, 4) = 1024 blocks x 256 threads -> single wave.
// Block (b, sc) sums rows [sc*49, sc*49+49); thread t owns float4 column t.
// Plain loads (measured faster than __ldcs on this stream: R5 vs R8).
// ---------------------------------------------------------------------------
__global__ void __launch_bounds__(256) k_mean_partial(const float* __restrict__ x) {
    int b  = blockIdx.x;
    int sc = blockIdx.y;
    int t  = threadIdx.x;
    const float4* xp = (const float4*)x + ((size_t)b * S + sc * 49) * (D / 4) + t;
    float ax = 0.f, ay = 0.f, az = 0.f, aw = 0.f;
#pragma unroll 7
    for (int s = 0; s < 49; s++) {
        float4 v = xp[(size_t)s * (D / 4)];
        ax += v.x; ay += v.y; az += v.z; aw += v.w;
    }
    ((float4*)g_qpart[sc])[b * (D / 4) + t] = make_float4(ax, ay, az, aw);
}

// ---------------------------------------------------------------------------
// K2: combine + normalize (queries and keys in one launch).
// grid 768 x 256:  [0,256) query b (sum partials; /196 cancels in normalize),
//                  [256,768) key p = bid-256.
// ---------------------------------------------------------------------------
__global__ void __launch_bounds__(256) k_combine(const float* __restrict__ key) {
    __shared__ float wsum[8];
    int bid = blockIdx.x;
    int t   = threadIdx.x;
    float4 v;
    float4* dst;
    if (bid < B) {
        float4 p0 = ((const float4*)g_qpart[0])[bid * (D / 4) + t];
        float4 p1 = ((const float4*)g_qpart[1])[bid * (D / 4) + t];
        float4 p2 = ((const float4*)g_qpart[2])[bid * (D / 4) + t];
        float4 p3 = ((const float4*)g_qpart[3])[bid * (D / 4) + t];
        v.x = (p0.x + p1.x) + (p2.x + p3.x);
        v.y = (p0.y + p1.y) + (p2.y + p3.y);
        v.z = (p0.z + p1.z) + (p2.z + p3.z);
        v.w = (p0.w + p1.w) + (p2.w + p3.w);
        dst = (float4*)g_qn + bid * (D / 4) + t;
    } else {
        int p = bid - B;
        v = ((const float4*)key)[p * (D / 4) + t];
        dst = (float4*)g_keyn + p * (D / 4) + t;
    }
    float ss = v.x * v.x + v.y * v.y + v.z * v.z + v.w * v.w;
#pragma unroll
    for (int o = 16; o > 0; o >>= 1) ss += __shfl_down_sync(0xffffffffu, ss, o);
    if ((t & 31) == 0) wsum[t >> 5] = ss;
    __syncthreads();
    float tot = ((wsum[0] + wsum[1]) + (wsum[2] + wsum[3])) +
                ((wsum[4] + wsum[5]) + (wsum[6] + wsum[7]));
    float rs = rsqrtf(fmaxf(tot, 1e-12f));
    v.x *= rs; v.y *= rs; v.z *= rs; v.w *= rs;
    *dst = v;
}

// ---------------------------------------------------------------------------
// K3: sim GEMM  sim[b,p] = dot(qn[b], keyn[p]).
// 128x128 tile, 256 threads, 8x8 outputs/thread (split-column mapping:
// rows {ty*4..+3, 64+ty*4..+3} x cols {tx*4..+3, 64+tx*4..+3}).
// Loader: lanes along ROW (conflict-free STS into [k][row] panels).
// grid(2, 4, KSPLIT) = 128 blocks, dynamic smem 2*KCH*PITCH floats.
// ---------------------------------------------------------------------------
extern __shared__ float s_gemm[];
__global__ void __launch_bounds__(256) k_sim_gemm() {
    float (*As)[PITCH] = (float(*)[PITCH])s_gemm;
    float (*Bs)[PITCH] = (float(*)[PITCH])(s_gemm + KCH * PITCH);
    int t  = threadIdx.x;
    int b0 = blockIdx.x * 128;
    int p0 = blockIdx.y * 128;
    int k0 = blockIdx.z * KCH;
    int tx = t & 15;
    int ty = t >> 4;

#pragma unroll
    for (int i = 0; i < 8; i++) {
        int id  = t + i * 256;
        int row = id & 127;
        int k4  = id >> 7;      // 0..15
        float4 a4 = *(const float4*)&g_qn  [(b0 + row) * D + k0 + k4 * 4];
        float4 b4 = *(const float4*)&g_keyn[(p0 + row) * D + k0 + k4 * 4];
        As[k4 * 4 + 0][row] = a4.x; As[k4 * 4 + 1][row] = a4.y;
        As[k4 * 4 + 2][row] = a4.z; As[k4 * 4 + 3][row] = a4.w;
        Bs[k4 * 4 + 0][row] = b4.x; Bs[k4 * 4 + 1][row] = b4.y;
        Bs[k4 * 4 + 2][row] = b4.z; Bs[k4 * 4 + 3][row] = b4.w;
    }
    __syncthreads();

    unsigned long long acc[8][4];
#pragma unroll
    for (int i = 0; i < 8; i++)
#pragma unroll
        for (int j = 0; j < 4; j++) acc[i][j] = 0ull;

#pragma unroll 4
    for (int k = 0; k < KCH; k++) {
        float4 av0 = *(const float4*)&As[k][ty * 4];
        float4 av1 = *(const float4*)&As[k][64 + ty * 4];
        float4 bv0 = *(const float4*)&Bs[k][tx * 4];
        float4 bv1 = *(const float4*)&Bs[k][64 + tx * 4];
        unsigned long long bp[4];
        bp[0] = pack2(bv0.x, bv0.y); bp[1] = pack2(bv0.z, bv0.w);
        bp[2] = pack2(bv1.x, bv1.y); bp[3] = pack2(bv1.z, bv1.w);
        float aa[8] = {av0.x, av0.y, av0.z, av0.w, av1.x, av1.y, av1.z, av1.w};
#pragma unroll
        for (int i = 0; i < 8; i++) {
            unsigned long long ad = pack2(aa[i], aa[i]);
#pragma unroll
            for (int j = 0; j < 4; j++) acc[i][j] = fma2(ad, bp[j], acc[i][j]);
        }
    }

    float* out = g_simpart[blockIdx.z];
#pragma unroll
    for (int i = 0; i < 8; i++) {
        int row = b0 + ((i < 4) ? (ty * 4 + i) : (64 + ty * 4 + (i - 4)));
        float4 r0, r1;
        unpack2(acc[i][0], r0.x, r0.y); unpack2(acc[i][1], r0.z, r0.w);
        unpack2(acc[i][2], r1.x, r1.y); unpack2(acc[i][3], r1.z, r1.w);
        *(float4*)&out[row * P + p0 + tx * 4]      = r0;
        *(float4*)&out[row * P + p0 + 64 + tx * 4] = r1;
    }
}

// ---------------------------------------------------------------------------
// K4: top-k selection (gumbel argmax == straight-through).  grid(B) x 512.
// Gumbel u for ALL 4 rounds loaded upfront (batched MLP) + ILP transform;
// the 4 argmax rounds then touch only registers/smem.  Writes g_idx.
// ---------------------------------------------------------------------------
__global__ void __launch_bounds__(512) k_select(const float* __restrict__ gu) {
    __shared__ float sval[P];
    __shared__ float rv[16];
    __shared__ int   ri[16];
    int b = blockIdx.x;
    int t = threadIdx.x;

    float u[TOPK], gn[TOPK];
#pragma unroll
    for (int i = 0; i < TOPK; i++)
        u[i] = __ldcs(&gu[((size_t)i * B + b) * P + t]);
#pragma unroll
    for (int i = 0; i < TOPK; i++)
        gn[i] = -logf(-logf(u[i] + 1e-10f) + 1e-10f);

    {
        float s = 0.f;
#pragma unroll
        for (int c = 0; c < KSPLIT; c++) s += g_simpart[c][b * P + t];
        sval[t] = s;
    }
    __syncthreads();

    for (int i = 0; i < TOPK; i++) {
        float bv = sval[t] + gn[i];
        int   bi = t;
#pragma unroll
        for (int o = 16; o > 0; o >>= 1) {
            float ov = __shfl_down_sync(0xffffffffu, bv, o);
            int   oi = __shfl_down_sync(0xffffffffu, bi, o);
            if (ov > bv || (ov == bv && oi < bi)) { bv = ov; bi = oi; }
        }
        if ((t & 31) == 0) { rv[t >> 5] = bv; ri[t >> 5] = bi; }
        __syncthreads();
        if (t == 0) {
            float fv = rv[0]; int fi = ri[0];
#pragma unroll
            for (int w = 1; w < 16; w++) {
                if (rv[w] > fv || (rv[w] == fv && ri[w] < fi)) { fv = rv[w]; fi = ri[w]; }
            }
            g_idx[i * B + b] = fi;
            sval[fi] -= 1000.0f;   // training-mode mask-out (w == hard numerically)
        }
        __syncthreads();
    }
}

// ---------------------------------------------------------------------------
// K5: gather.  grid(B*TOPK) = 1024 blocks x 256 threads (single full wave).
// out[b, i*L:(i+1)*L, :] = prompt[g_idx[i][b]]   (32 KB per block)
// ---------------------------------------------------------------------------
__global__ void __launch_bounds__(256) k_gather(const float* __restrict__ prompt,
                                                float* __restrict__ out) {
    int bid = blockIdx.x;
    int b   = bid >> 2;
    int i   = bid & 3;
    int idx = g_idx[i * B + b];
    const float4* src = (const float4*)prompt + (size_t)idx * (L * D / 4);
    float4*       dst = (float4*)out + (size_t)b * (TOPK * L * D / 4) + i * (L * D / 4);
    int t = threadIdx.x;
#pragma unroll
    for (int j = 0; j < (L * D / 4) / 256; j++)
        __stcs(&dst[t + j * 256], src[t + j * 256]);
}

// ---------------------------------------------------------------------------
extern "C" void kernel_launch(void* const* d_in, const int* in_sizes, int n_in,
                              void* d_out, int out_size) {
    const float* x_embed    = (const float*)d_in[0];
    const float* prompt     = (const float*)d_in[1];
    const float* prompt_key = (const float*)d_in[2];
    const float* gumbel_u   = (const float*)d_in[3];
    float* out = (float*)d_out;

    const int gemm_smem = 2 * KCH * PITCH * (int)sizeof(float);  // 67584 B
    cudaFuncSetAttribute(k_sim_gemm, cudaFuncAttributeMaxDynamicSharedMemorySize,
                         gemm_smem);

    k_mean_partial <<<dim3(B, 4), 256>>>(x_embed);
    k_combine      <<<B + P, 256>>>(prompt_key);
    k_sim_gemm     <<<dim3(B / 128, P / 128, KSPLIT), 256, gemm_smem>>>();
    k_select       <<<B, 512>>>(gumbel_u);
    k_gather       <<<B * TOPK, 256>>>(prompt, out);
}

// round 11
// speedup vs baseline: 1.0683x; 1.0683x over previous
#include <cuda_runtime.h>
#include <cuda_bf16.h>
#include <math.h>

// Problem constants
#define B    256
#define S    196
#define D    1024
#define P    512
#define L    8
#define TOPK 4

// k-split for sim GEMM
#define KSPLIT 16
#define KCH    (D / KSPLIT)   // 64
#define PITCH  132            // float4-aligned, conflict-free compute reads

// Scratch (no cudaMalloc allowed)
__device__ float g_qn[B * D];              // normalized query
__device__ float g_keyn[P * D];            // normalized keys
__device__ float g_simpart[KSPLIT][B * P]; // partial sims

// ---------------------------------------------------------------------------
// f32x2 packed-FMA helpers (two independent IEEE fp32 FMAs per instr)
// ---------------------------------------------------------------------------
__device__ __forceinline__ unsigned long long fma2(unsigned long long a,
                                                   unsigned long long b,
                                                   unsigned long long c) {
    unsigned long long d;
    asm("fma.rn.f32x2 %0, %1, %2, %3;" : "=l"(d) : "l"(a), "l"(b), "l"(c));
    return d;
}
__device__ __forceinline__ unsigned long long pack2(float x, float y) {
    unsigned long long d;
    asm("mov.b64 %0, {%1, %2};" : "=l"(d) : "f"(x), "f"(y));
    return d;
}
__device__ __forceinline__ void unpack2(unsigned long long v, float& x, float& y) {
    asm("mov.b64 {%0, %1}, %2;" : "=f"(x), "=f"(y) : "l"(v));
}

// ---------------------------------------------------------------------------
// K1 (fused roles): grid 384 blocks x 1024 threads.
//  blocks [0,256):  query b: mean over S (the /196 cancels in normalize) +
//                   L2-normalize.  Thread = (s_chunk, d4), plain float4 loads
//                   (measured faster than __ldcs: R5 vs R8).
//  blocks [256,384): keys: 4 keys per block, 256 threads (float4) per key.
// ---------------------------------------------------------------------------
__global__ void __launch_bounds__(1024) k_prep(const float* __restrict__ x,
                                               const float* __restrict__ key) {
    int bid = blockIdx.x;
    int t   = threadIdx.x;
    if (bid < B) {
        __shared__ float4 part[4][256];   // 16 KB
        __shared__ float  wsum[8];
        int sc = t >> 8;          // s-chunk 0..3 (49 rows each)
        int d4 = t & 255;         // float4 column
        const float4* xp = (const float4*)x + ((size_t)bid * S + sc * 49) * (D / 4) + d4;
        float ax = 0.f, ay = 0.f, az = 0.f, aw = 0.f;
#pragma unroll 7
        for (int s = 0; s < 49; s++) {
            float4 v = xp[(size_t)s * (D / 4)];
            ax += v.x; ay += v.y; az += v.z; aw += v.w;
        }
        part[sc][d4] = make_float4(ax, ay, az, aw);
        __syncthreads();
        float4 v;
        if (t < 256) {
            float4 p0 = part[0][t], p1 = part[1][t], p2 = part[2][t], p3 = part[3][t];
            v.x = (p0.x + p1.x) + (p2.x + p3.x);
            v.y = (p0.y + p1.y) + (p2.y + p3.y);
            v.z = (p0.z + p1.z) + (p2.z + p3.z);
            v.w = (p0.w + p1.w) + (p2.w + p3.w);
            float ss = v.x * v.x + v.y * v.y + v.z * v.z + v.w * v.w;
#pragma unroll
            for (int o = 16; o > 0; o >>= 1) ss += __shfl_down_sync(0xffffffffu, ss, o);
            if ((t & 31) == 0) wsum[t >> 5] = ss;
        }
        __syncthreads();
        if (t < 256) {
            float tot = ((wsum[0] + wsum[1]) + (wsum[2] + wsum[3])) +
                        ((wsum[4] + wsum[5]) + (wsum[6] + wsum[7]));
            float rs = rsqrtf(fmaxf(tot, 1e-12f));
            v.x *= rs; v.y *= rs; v.z *= rs; v.w *= rs;
            ((float4*)g_qn)[bid * (D / 4) + t] = v;
        }
    } else {
        // ---- key-normalize role: 4 keys per block ----
        __shared__ float kw[4][8];
        int g = t >> 8;
        int l = t & 255;
        int p = (bid - B) * 4 + g;
        float4 v = ((const float4*)key)[p * (D / 4) + l];
        float ss = v.x * v.x + v.y * v.y + v.z * v.z + v.w * v.w;
#pragma unroll
        for (int o = 16; o > 0; o >>= 1) ss += __shfl_down_sync(0xffffffffu, ss, o);
        if ((l & 31) == 0) kw[g][l >> 5] = ss;
        __syncthreads();
        float s2 = ((kw[g][0] + kw[g][1]) + (kw[g][2] + kw[g][3])) +
                   ((kw[g][4] + kw[g][5]) + (kw[g][6] + kw[g][7]));
        float rs = rsqrtf(fmaxf(s2, 1e-12f));
        v.x *= rs; v.y *= rs; v.z *= rs; v.w *= rs;
        ((float4*)g_keyn)[p * (D / 4) + l] = v;
    }
}

// ---------------------------------------------------------------------------
// K2: sim GEMM  sim[b,p] = dot(qn[b], keyn[p]).
// 128x128 tile, 256 threads, 8x8 outputs/thread (split-column mapping:
// rows {ty*4..+3, 64+ty*4..+3} x cols {tx*4..+3, 64+tx*4..+3}).
// Loader: lanes along ROW (conflict-free STS into [k][row] panels).
// grid(2, 4, KSPLIT) = 128 blocks, dynamic smem 2*KCH*PITCH floats.
// ---------------------------------------------------------------------------
extern __shared__ float s_gemm[];
__global__ void __launch_bounds__(256) k_sim_gemm() {
    float (*As)[PITCH] = (float(*)[PITCH])s_gemm;
    float (*Bs)[PITCH] = (float(*)[PITCH])(s_gemm + KCH * PITCH);
    int t  = threadIdx.x;
    int b0 = blockIdx.x * 128;
    int p0 = blockIdx.y * 128;
    int k0 = blockIdx.z * KCH;
    int tx = t & 15;
    int ty = t >> 4;

#pragma unroll
    for (int i = 0; i < 8; i++) {
        int id  = t + i * 256;
        int row = id & 127;
        int k4  = id >> 7;      // 0..15
        float4 a4 = *(const float4*)&g_qn  [(b0 + row) * D + k0 + k4 * 4];
        float4 b4 = *(const float4*)&g_keyn[(p0 + row) * D + k0 + k4 * 4];
        As[k4 * 4 + 0][row] = a4.x; As[k4 * 4 + 1][row] = a4.y;
        As[k4 * 4 + 2][row] = a4.z; As[k4 * 4 + 3][row] = a4.w;
        Bs[k4 * 4 + 0][row] = b4.x; Bs[k4 * 4 + 1][row] = b4.y;
        Bs[k4 * 4 + 2][row] = b4.z; Bs[k4 * 4 + 3][row] = b4.w;
    }
    __syncthreads();

    unsigned long long acc[8][4];
#pragma unroll
    for (int i = 0; i < 8; i++)
#pragma unroll
        for (int j = 0; j < 4; j++) acc[i][j] = 0ull;

#pragma unroll 4
    for (int k = 0; k < KCH; k++) {
        float4 av0 = *(const float4*)&As[k][ty * 4];
        float4 av1 = *(const float4*)&As[k][64 + ty * 4];
        float4 bv0 = *(const float4*)&Bs[k][tx * 4];
        float4 bv1 = *(const float4*)&Bs[k][64 + tx * 4];
        unsigned long long bp[4];
        bp[0] = pack2(bv0.x, bv0.y); bp[1] = pack2(bv0.z, bv0.w);
        bp[2] = pack2(bv1.x, bv1.y); bp[3] = pack2(bv1.z, bv1.w);
        float aa[8] = {av0.x, av0.y, av0.z, av0.w, av1.x, av1.y, av1.z, av1.w};
#pragma unroll
        for (int i = 0; i < 8; i++) {
            unsigned long long ad = pack2(aa[i], aa[i]);
#pragma unroll
            for (int j = 0; j < 4; j++) acc[i][j] = fma2(ad, bp[j], acc[i][j]);
        }
    }

    float* out = g_simpart[blockIdx.z];
#pragma unroll
    for (int i = 0; i < 8; i++) {
        int row = b0 + ((i < 4) ? (ty * 4 + i) : (64 + ty * 4 + (i - 4)));
        float4 r0, r1;
        unpack2(acc[i][0], r0.x, r0.y); unpack2(acc[i][1], r0.z, r0.w);
        unpack2(acc[i][2], r1.x, r1.y); unpack2(acc[i][3], r1.z, r1.w);
        *(float4*)&out[row * P + p0 + tx * 4]      = r0;
        *(float4*)&out[row * P + p0 + 64 + tx * 4] = r1;
    }
}

// ---------------------------------------------------------------------------
// K3: fused top-k selection + gather.  grid(B, 2) = 512 blocks x 512 threads.
// Both blocks of a given b run the IDENTICAL deterministic selection (the
// duplication is latency-parallel and free); each block then copies half of
// the 128 KB output -> copy parallelism doubles vs grid(B).
// Gumbel u for all 4 rounds loaded upfront (batched MLP) + ILP transform.
// ---------------------------------------------------------------------------
__global__ void __launch_bounds__(512) k_select_gather(const float* __restrict__ gu,
                                                       const float* __restrict__ prompt,
                                                       float* __restrict__ out) {
    __shared__ float sval[P];
    __shared__ float rv[16];
    __shared__ int   ri[16];
    __shared__ int   sidx[TOPK];
    int b = blockIdx.x;
    int h = blockIdx.y;     // output half 0/1
    int t = threadIdx.x;

    // batched gumbel load + transform (read-once -> streaming loads)
    float u[TOPK], gn[TOPK];
#pragma unroll
    for (int i = 0; i < TOPK; i++)
        u[i] = __ldcs(&gu[((size_t)i * B + b) * P + t]);
#pragma unroll
    for (int i = 0; i < TOPK; i++)
        gn[i] = -logf(-logf(u[i] + 1e-10f) + 1e-10f);

    {
        float s = 0.f;
#pragma unroll
        for (int c = 0; c < KSPLIT; c++) s += g_simpart[c][b * P + t];
        sval[t] = s;
    }
    __syncthreads();

    for (int i = 0; i < TOPK; i++) {
        float bv = sval[t] + gn[i];
        int   bi = t;
#pragma unroll
        for (int o = 16; o > 0; o >>= 1) {
            float ov = __shfl_down_sync(0xffffffffu, bv, o);
            int   oi = __shfl_down_sync(0xffffffffu, bi, o);
            if (ov > bv || (ov == bv && oi < bi)) { bv = ov; bi = oi; }
        }
        if ((t & 31) == 0) { rv[t >> 5] = bv; ri[t >> 5] = bi; }
        __syncthreads();
        if (t == 0) {
            float fv = rv[0]; int fi = ri[0];
#pragma unroll
            for (int w = 1; w < 16; w++) {
                if (rv[w] > fv || (rv[w] == fv && ri[w] < fi)) { fv = rv[w]; fi = ri[w]; }
            }
            sidx[i] = fi;
            sval[fi] -= 1000.0f;   // training-mode mask-out (w == hard numerically)
        }
        __syncthreads();
    }

    // copy this block's half: out[b, h*2L:(h+1)*2L, :]  (64 KB)
    // streaming stores: output is written once, never re-read.
    float4* dst = (float4*)out + (size_t)b * (TOPK * L * D / 4);
#pragma unroll
    for (int v = 0; v < TOPK * L * D / 8; v += 512) {
        int vv  = h * (TOPK * L * D / 8) + v + t;
        int i   = vv >> 11;            // L*D/4 = 2048 float4 per selection
        int off = vv & 2047;
        const float4* src = (const float4*)prompt + (size_t)sidx[i] * (L * D / 4);
        __stcs(&dst[vv], src[off]);
    }
}

// ---------------------------------------------------------------------------
extern "C" void kernel_launch(void* const* d_in, const int* in_sizes, int n_in,
                              void* d_out, int out_size) {
    const float* x_embed    = (const float*)d_in[0];
    const float* prompt     = (const float*)d_in[1];
    const float* prompt_key = (const float*)d_in[2];
    const float* gumbel_u   = (const float*)d_in[3];
    float* out = (float*)d_out;

    const int gemm_smem = 2 * KCH * PITCH * (int)sizeof(float);  // 67584 B
    cudaFuncSetAttribute(k_sim_gemm, cudaFuncAttributeMaxDynamicSharedMemorySize,
                         gemm_smem);

    k_prep         <<<B + P / 4, 1024>>>(x_embed, prompt_key);
    k_sim_gemm     <<<dim3(B / 128, P / 128, KSPLIT), 256, gemm_smem>>>();
    k_select_gather<<<dim3(B, 2), 512>>>(gumbel_u, prompt, out);
}

// round 14
// speedup vs baseline: 1.1742x; 1.0991x over previous
#include <cuda_runtime.h>
#include <cuda_bf16.h>
#include <math.h>

// Problem constants
#define B    256
#define S    196
#define D    1024
#define P    512
#define L    8
#define TOPK 4

// k-split for sim GEMM
#define KSPLIT 16
#define KCH    (D / KSPLIT)   // 64
#define PITCH  132            // float4-aligned, conflict-free compute reads

// Scratch (no cudaMalloc allowed)
__device__ float g_qn[B * D];              // normalized query
__device__ float g_keyn[P * D];            // normalized keys
__device__ float g_simpart[KSPLIT][B * P]; // partial sims

// ---------------------------------------------------------------------------
// f32x2 packed-FMA helpers (two independent IEEE fp32 FMAs per instr)
// ---------------------------------------------------------------------------
__device__ __forceinline__ unsigned long long fma2(unsigned long long a,
                                                   unsigned long long b,
                                                   unsigned long long c) {
    unsigned long long d;
    asm("fma.rn.f32x2 %0, %1, %2, %3;" : "=l"(d) : "l"(a), "l"(b), "l"(c));
    return d;
}
__device__ __forceinline__ unsigned long long pack2(float x, float y) {
    unsigned long long d;
    asm("mov.b64 %0, {%1, %2};" : "=l"(d) : "f"(x), "f"(y));
    return d;
}
__device__ __forceinline__ void unpack2(unsigned long long v, float& x, float& y) {
    asm("mov.b64 {%0, %1}, %2;" : "=f"(x), "=f"(y) : "l"(v));
}

// ---------------------------------------------------------------------------
// K1 (fused roles): grid 384 blocks x 1024 threads.  (R8-identical)
//  blocks [0,256):  query b: mean over S (the /196 cancels in normalize) +
//                   L2-normalize.  Thread = (s_chunk, d4): float4 streaming.
//  blocks [256,384): keys: 4 keys per block, 256 threads (float4) per key.
// ---------------------------------------------------------------------------
__global__ void __launch_bounds__(1024) k_prep(const float* __restrict__ x,
                                               const float* __restrict__ key) {
    int bid = blockIdx.x;
    int t   = threadIdx.x;
    if (bid < B) {
        __shared__ float4 part[4][256];   // 16 KB
        __shared__ float  wsum[8];
        int sc = t >> 8;          // s-chunk 0..3 (49 rows each)
        int d4 = t & 255;         // float4 column
        const float4* xp = (const float4*)x + ((size_t)bid * S + sc * 49) * (D / 4) + d4;
        float ax = 0.f, ay = 0.f, az = 0.f, aw = 0.f;
#pragma unroll 7
        for (int s = 0; s < 49; s++) {
            float4 v = __ldcs(&xp[(size_t)s * (D / 4)]);
            ax += v.x; ay += v.y; az += v.z; aw += v.w;
        }
        part[sc][d4] = make_float4(ax, ay, az, aw);
        __syncthreads();
        float4 v;
        if (t < 256) {
            float4 p0 = part[0][t], p1 = part[1][t], p2 = part[2][t], p3 = part[3][t];
            v.x = (p0.x + p1.x) + (p2.x + p3.x);
            v.y = (p0.y + p1.y) + (p2.y + p3.y);
            v.z = (p0.z + p1.z) + (p2.z + p3.z);
            v.w = (p0.w + p1.w) + (p2.w + p3.w);
            float ss = v.x * v.x + v.y * v.y + v.z * v.z + v.w * v.w;
#pragma unroll
            for (int o = 16; o > 0; o >>= 1) ss += __shfl_down_sync(0xffffffffu, ss, o);
            if ((t & 31) == 0) wsum[t >> 5] = ss;
        }
        __syncthreads();
        if (t < 256) {
            float tot = ((wsum[0] + wsum[1]) + (wsum[2] + wsum[3])) +
                        ((wsum[4] + wsum[5]) + (wsum[6] + wsum[7]));
            float rs = rsqrtf(fmaxf(tot, 1e-12f));
            v.x *= rs; v.y *= rs; v.z *= rs; v.w *= rs;
            ((float4*)g_qn)[bid * (D / 4) + t] = v;
        }
    } else {
        // ---- key-normalize role: 4 keys per block ----
        __shared__ float kw[4][8];
        int g = t >> 8;
        int l = t & 255;
        int p = (bid - B) * 4 + g;
        float4 v = ((const float4*)key)[p * (D / 4) + l];
        float ss = v.x * v.x + v.y * v.y + v.z * v.z + v.w * v.w;
#pragma unroll
        for (int o = 16; o > 0; o >>= 1) ss += __shfl_down_sync(0xffffffffu, ss, o);
        if ((l & 31) == 0) kw[g][l >> 5] = ss;
        __syncthreads();
        float s2 = ((kw[g][0] + kw[g][1]) + (kw[g][2] + kw[g][3])) +
                   ((kw[g][4] + kw[g][5]) + (kw[g][6] + kw[g][7]));
        float rs = rsqrtf(fmaxf(s2, 1e-12f));
        v.x *= rs; v.y *= rs; v.z *= rs; v.w *= rs;
        ((float4*)g_keyn)[p * (D / 4) + l] = v;
    }
}

// ---------------------------------------------------------------------------
// K2: sim GEMM  sim[b,p] = dot(qn[b], keyn[p]).  (R8-identical)
// 128x128 tile, 256 threads, 8x8 outputs/thread (split-column mapping).
// Loader: lanes along ROW (conflict-free STS into [k][row] panels).
// grid(2, 4, KSPLIT) = 128 blocks, dynamic smem 2*KCH*PITCH floats.
// ---------------------------------------------------------------------------
extern __shared__ float s_gemm[];
__global__ void __launch_bounds__(256) k_sim_gemm() {
    float (*As)[PITCH] = (float(*)[PITCH])s_gemm;
    float (*Bs)[PITCH] = (float(*)[PITCH])(s_gemm + KCH * PITCH);
    int t  = threadIdx.x;
    int b0 = blockIdx.x * 128;
    int p0 = blockIdx.y * 128;
    int k0 = blockIdx.z * KCH;
    int tx = t & 15;
    int ty = t >> 4;

#pragma unroll
    for (int i = 0; i < 8; i++) {
        int id  = t + i * 256;
        int row = id & 127;
        int k4  = id >> 7;      // 0..15
        float4 a4 = *(const float4*)&g_qn  [(b0 + row) * D + k0 + k4 * 4];
        float4 b4 = *(const float4*)&g_keyn[(p0 + row) * D + k0 + k4 * 4];
        As[k4 * 4 + 0][row] = a4.x; As[k4 * 4 + 1][row] = a4.y;
        As[k4 * 4 + 2][row] = a4.z; As[k4 * 4 + 3][row] = a4.w;
        Bs[k4 * 4 + 0][row] = b4.x; Bs[k4 * 4 + 1][row] = b4.y;
        Bs[k4 * 4 + 2][row] = b4.z; Bs[k4 * 4 + 3][row] = b4.w;
    }
    __syncthreads();

    unsigned long long acc[8][4];
#pragma unroll
    for (int i = 0; i < 8; i++)
#pragma unroll
        for (int j = 0; j < 4; j++) acc[i][j] = 0ull;

#pragma unroll 4
    for (int k = 0; k < KCH; k++) {
        float4 av0 = *(const float4*)&As[k][ty * 4];
        float4 av1 = *(const float4*)&As[k][64 + ty * 4];
        float4 bv0 = *(const float4*)&Bs[k][tx * 4];
        float4 bv1 = *(const float4*)&Bs[k][64 + tx * 4];
        unsigned long long bp[4];
        bp[0] = pack2(bv0.x, bv0.y); bp[1] = pack2(bv0.z, bv0.w);
        bp[2] = pack2(bv1.x, bv1.y); bp[3] = pack2(bv1.z, bv1.w);
        float aa[8] = {av0.x, av0.y, av0.z, av0.w, av1.x, av1.y, av1.z, av1.w};
#pragma unroll
        for (int i = 0; i < 8; i++) {
            unsigned long long ad = pack2(aa[i], aa[i]);
#pragma unroll
            for (int j = 0; j < 4; j++) acc[i][j] = fma2(ad, bp[j], acc[i][j]);
        }
    }

    float* out = g_simpart[blockIdx.z];
#pragma unroll
    for (int i = 0; i < 8; i++) {
        int row = b0 + ((i < 4) ? (ty * 4 + i) : (64 + ty * 4 + (i - 4)));
        float4 r0, r1;
        unpack2(acc[i][0], r0.x, r0.y); unpack2(acc[i][1], r0.z, r0.w);
        unpack2(acc[i][2], r1.x, r1.y); unpack2(acc[i][3], r1.z, r1.w);
        *(float4*)&out[row * P + p0 + tx * 4]      = r0;
        *(float4*)&out[row * P + p0 + 64 + tx * 4] = r1;
    }
}

// ---------------------------------------------------------------------------
// K3: fused top-k selection + gather.  grid(B), block 1024.
// Selection runs on threads t<512 (math identical to R8 -> same indices);
// the bulk copy then uses ALL 32 warps (2x store-issue width vs R8).
// ---------------------------------------------------------------------------
__global__ void __launch_bounds__(1024) k_select_gather(const float* __restrict__ gu,
                                                        const float* __restrict__ prompt,
                                                        float* __restrict__ out) {
    __shared__ float sval[P];
    __shared__ float rv[16];
    __shared__ int   ri[16];
    __shared__ int   sidx[TOPK];
    int b = blockIdx.x;
    int t = threadIdx.x;

    // batched gumbel load + transform (selection threads only)
    float gn[TOPK];
    if (t < P) {
        float u[TOPK];
#pragma unroll
        for (int i = 0; i < TOPK; i++)
            u[i] = __ldcs(&gu[((size_t)i * B + b) * P + t]);
#pragma unroll
        for (int i = 0; i < TOPK; i++)
            gn[i] = -logf(-logf(u[i] + 1e-10f) + 1e-10f);

        float s = 0.f;
#pragma unroll
        for (int c = 0; c < KSPLIT; c++) s += g_simpart[c][b * P + t];
        sval[t] = s;
    }
    __syncthreads();

    for (int i = 0; i < TOPK; i++) {
        if (t < P) {
            float bv = sval[t] + gn[i];
            int   bi = t;
#pragma unroll
            for (int o = 16; o > 0; o >>= 1) {
                float ov = __shfl_down_sync(0xffffffffu, bv, o);
                int   oi = __shfl_down_sync(0xffffffffu, bi, o);
                if (ov > bv || (ov == bv && oi < bi)) { bv = ov; bi = oi; }
            }
            if ((t & 31) == 0) { rv[t >> 5] = bv; ri[t >> 5] = bi; }
        }
        __syncthreads();
        if (t == 0) {
            float fv = rv[0]; int fi = ri[0];
#pragma unroll
            for (int w = 1; w < 16; w++) {
                if (rv[w] > fv || (rv[w] == fv && ri[w] < fi)) { fv = rv[w]; fi = ri[w]; }
            }
            sidx[i] = fi;
            sval[fi] -= 1000.0f;   // training-mode mask-out (w == hard numerically)
        }
        __syncthreads();
    }

    // bulk copy with all 1024 threads: out[b, i*L:(i+1)*L, :] = prompt[sidx[i]]
    // streaming stores: output is written once, never re-read.
    float4* dst = (float4*)out + (size_t)b * (TOPK * L * D / 4);
#pragma unroll
    for (int v = 0; v < TOPK * L * D / 4; v += 1024) {
        int vv  = v + t;
        int i   = vv >> 11;            // L*D/4 = 2048 float4 per selection
        int off = vv & 2047;
        const float4* src = (const float4*)prompt + (size_t)sidx[i] * (L * D / 4);
        __stcs(&dst[vv], src[off]);
    }
}

// ---------------------------------------------------------------------------
extern "C" void kernel_launch(void* const* d_in, const int* in_sizes, int n_in,
                              void* d_out, int out_size) {
    const float* x_embed    = (const float*)d_in[0];
    const float* prompt     = (const float*)d_in[1];
    const float* prompt_key = (const float*)d_in[2];
    const float* gumbel_u   = (const float*)d_in[3];
    float* out = (float*)d_out;

    const int gemm_smem = 2 * KCH * PITCH * (int)sizeof(float);  // 67584 B
    cudaFuncSetAttribute(k_sim_gemm, cudaFuncAttributeMaxDynamicSharedMemorySize,
                         gemm_smem);

    k_prep         <<<B + P / 4, 1024>>>(x_embed, prompt_key);
    k_sim_gemm     <<<dim3(B / 128, P / 128, KSPLIT), 256, gemm_smem>>>();
    k_select_gather<<<B, 1024>>>(gumbel_u, prompt, out);
}

// round 15
// speedup vs baseline: 1.1944x; 1.0173x over previous
#include <cuda_runtime.h>
#include <cuda_bf16.h>
#include <math.h>

// Problem constants
#define B    256
#define S    196
#define D    1024
#define P    512
#define L    8
#define TOPK 4

// k-split for sim GEMM
#define KSPLIT 16
#define KCH    (D / KSPLIT)   // 64
#define PITCH  132            // float4-aligned, conflict-free compute reads

// Scratch (no cudaMalloc allowed)
__device__ float g_qn[B * D];              // normalized query
__device__ float g_keyn[P * D];            // normalized keys
__device__ float g_simpart[KSPLIT][B * P]; // partial sims

// ---------------------------------------------------------------------------
// f32x2 packed-FMA helpers (two independent IEEE fp32 FMAs per instr)
// ---------------------------------------------------------------------------
__device__ __forceinline__ unsigned long long fma2(unsigned long long a,
                                                   unsigned long long b,
                                                   unsigned long long c) {
    unsigned long long d;
    asm("fma.rn.f32x2 %0, %1, %2, %3;" : "=l"(d) : "l"(a), "l"(b), "l"(c));
    return d;
}
__device__ __forceinline__ unsigned long long pack2(float x, float y) {
    unsigned long long d;
    asm("mov.b64 %0, {%1, %2};" : "=l"(d) : "f"(x), "f"(y));
    return d;
}
__device__ __forceinline__ void unpack2(unsigned long long v, float& x, float& y) {
    asm("mov.b64 {%0, %1}, %2;" : "=f"(x), "=f"(y) : "l"(v));
}

// ---------------------------------------------------------------------------
// K1 (fused roles): grid 384 blocks x 1024 threads.  (R8-identical)
//  blocks [0,256):  query b: mean over S (the /196 cancels in normalize) +
//                   L2-normalize.  Thread = (s_chunk, d4): float4 streaming.
//  blocks [256,384): keys: 4 keys per block, 256 threads (float4) per key.
// ---------------------------------------------------------------------------
__global__ void __launch_bounds__(1024) k_prep(const float* __restrict__ x,
                                               const float* __restrict__ key) {
    int bid = blockIdx.x;
    int t   = threadIdx.x;
    if (bid < B) {
        __shared__ float4 part[4][256];   // 16 KB
        __shared__ float  wsum[8];
        int sc = t >> 8;          // s-chunk 0..3 (49 rows each)
        int d4 = t & 255;         // float4 column
        const float4* xp = (const float4*)x + ((size_t)bid * S + sc * 49) * (D / 4) + d4;
        float ax = 0.f, ay = 0.f, az = 0.f, aw = 0.f;
#pragma unroll 7
        for (int s = 0; s < 49; s++) {
            float4 v = __ldcs(&xp[(size_t)s * (D / 4)]);
            ax += v.x; ay += v.y; az += v.z; aw += v.w;
        }
        part[sc][d4] = make_float4(ax, ay, az, aw);
        __syncthreads();
        float4 v;
        if (t < 256) {
            float4 p0 = part[0][t], p1 = part[1][t], p2 = part[2][t], p3 = part[3][t];
            v.x = (p0.x + p1.x) + (p2.x + p3.x);
            v.y = (p0.y + p1.y) + (p2.y + p3.y);
            v.z = (p0.z + p1.z) + (p2.z + p3.z);
            v.w = (p0.w + p1.w) + (p2.w + p3.w);
            float ss = v.x * v.x + v.y * v.y + v.z * v.z + v.w * v.w;
#pragma unroll
            for (int o = 16; o > 0; o >>= 1) ss += __shfl_down_sync(0xffffffffu, ss, o);
            if ((t & 31) == 0) wsum[t >> 5] = ss;
        }
        __syncthreads();
        if (t < 256) {
            float tot = ((wsum[0] + wsum[1]) + (wsum[2] + wsum[3])) +
                        ((wsum[4] + wsum[5]) + (wsum[6] + wsum[7]));
            float rs = rsqrtf(fmaxf(tot, 1e-12f));
            v.x *= rs; v.y *= rs; v.z *= rs; v.w *= rs;
            ((float4*)g_qn)[bid * (D / 4) + t] = v;
        }
    } else {
        // ---- key-normalize role: 4 keys per block ----
        __shared__ float kw[4][8];
        int g = t >> 8;
        int l = t & 255;
        int p = (bid - B) * 4 + g;
        float4 v = ((const float4*)key)[p * (D / 4) + l];
        float ss = v.x * v.x + v.y * v.y + v.z * v.z + v.w * v.w;
#pragma unroll
        for (int o = 16; o > 0; o >>= 1) ss += __shfl_down_sync(0xffffffffu, ss, o);
        if ((l & 31) == 0) kw[g][l >> 5] = ss;
        __syncthreads();
        float s2 = ((kw[g][0] + kw[g][1]) + (kw[g][2] + kw[g][3])) +
                   ((kw[g][4] + kw[g][5]) + (kw[g][6] + kw[g][7]));
        float rs = rsqrtf(fmaxf(s2, 1e-12f));
        v.x *= rs; v.y *= rs; v.z *= rs; v.w *= rs;
        ((float4*)g_keyn)[p * (D / 4) + l] = v;
    }
}

// ---------------------------------------------------------------------------
// K2: sim GEMM  sim[b,p] = dot(qn[b], keyn[p]).  (R8-identical)
// 128x128 tile, 256 threads, 8x8 outputs/thread (split-column mapping).
// Loader: lanes along ROW (conflict-free STS into [k][row] panels).
// grid(2, 4, KSPLIT) = 128 blocks, dynamic smem 2*KCH*PITCH floats.
// ---------------------------------------------------------------------------
extern __shared__ float s_gemm[];
__global__ void __launch_bounds__(256) k_sim_gemm() {
    float (*As)[PITCH] = (float(*)[PITCH])s_gemm;
    float (*Bs)[PITCH] = (float(*)[PITCH])(s_gemm + KCH * PITCH);
    int t  = threadIdx.x;
    int b0 = blockIdx.x * 128;
    int p0 = blockIdx.y * 128;
    int k0 = blockIdx.z * KCH;
    int tx = t & 15;
    int ty = t >> 4;

#pragma unroll
    for (int i = 0; i < 8; i++) {
        int id  = t + i * 256;
        int row = id & 127;
        int k4  = id >> 7;      // 0..15
        float4 a4 = *(const float4*)&g_qn  [(b0 + row) * D + k0 + k4 * 4];
        float4 b4 = *(const float4*)&g_keyn[(p0 + row) * D + k0 + k4 * 4];
        As[k4 * 4 + 0][row] = a4.x; As[k4 * 4 + 1][row] = a4.y;
        As[k4 * 4 + 2][row] = a4.z; As[k4 * 4 + 3][row] = a4.w;
        Bs[k4 * 4 + 0][row] = b4.x; Bs[k4 * 4 + 1][row] = b4.y;
        Bs[k4 * 4 + 2][row] = b4.z; Bs[k4 * 4 + 3][row] = b4.w;
    }
    __syncthreads();

    unsigned long long acc[8][4];
#pragma unroll
    for (int i = 0; i < 8; i++)
#pragma unroll
        for (int j = 0; j < 4; j++) acc[i][j] = 0ull;

#pragma unroll 4
    for (int k = 0; k < KCH; k++) {
        float4 av0 = *(const float4*)&As[k][ty * 4];
        float4 av1 = *(const float4*)&As[k][64 + ty * 4];
        float4 bv0 = *(const float4*)&Bs[k][tx * 4];
        float4 bv1 = *(const float4*)&Bs[k][64 + tx * 4];
        unsigned long long bp[4];
        bp[0] = pack2(bv0.x, bv0.y); bp[1] = pack2(bv0.z, bv0.w);
        bp[2] = pack2(bv1.x, bv1.y); bp[3] = pack2(bv1.z, bv1.w);
        float aa[8] = {av0.x, av0.y, av0.z, av0.w, av1.x, av1.y, av1.z, av1.w};
#pragma unroll
        for (int i = 0; i < 8; i++) {
            unsigned long long ad = pack2(aa[i], aa[i]);
#pragma unroll
            for (int j = 0; j < 4; j++) acc[i][j] = fma2(ad, bp[j], acc[i][j]);
        }
    }

    float* out = g_simpart[blockIdx.z];
#pragma unroll
    for (int i = 0; i < 8; i++) {
        int row = b0 + ((i < 4) ? (ty * 4 + i) : (64 + ty * 4 + (i - 4)));
        float4 r0, r1;
        unpack2(acc[i][0], r0.x, r0.y); unpack2(acc[i][1], r0.z, r0.w);
        unpack2(acc[i][2], r1.x, r1.y); unpack2(acc[i][3], r1.z, r1.w);
        *(float4*)&out[row * P + p0 + tx * 4]      = r0;
        *(float4*)&out[row * P + p0 + 64 + tx * 4] = r1;
    }
}

// ---------------------------------------------------------------------------
// K3: fused top-k selection + gather.  grid(B), block 512 (one p per thread).
// Selection identical to R8.  Copy phase uses explicit load-batching: 4
// independent LDG.128 staged in registers before their 4 STG.128, so each
// warp keeps 4 loads in flight (vs ~1 with interleaved ld/st) -> in-flight
// bytes per SM rise ~4x, lifting the copy off its latency-BW ceiling.
// ---------------------------------------------------------------------------
__global__ void __launch_bounds__(512, 2) k_select_gather(const float* __restrict__ gu,
                                                          const float* __restrict__ prompt,
                                                          float* __restrict__ out) {
    __shared__ float sval[P];
    __shared__ float rv[16];
    __shared__ int   ri[16];
    __shared__ int   sidx[TOPK];
    int b = blockIdx.x;
    int t = threadIdx.x;

    // batched gumbel load + transform (read-once -> streaming loads)
    float u[TOPK], gn[TOPK];
#pragma unroll
    for (int i = 0; i < TOPK; i++)
        u[i] = __ldcs(&gu[((size_t)i * B + b) * P + t]);
#pragma unroll
    for (int i = 0; i < TOPK; i++)
        gn[i] = -logf(-logf(u[i] + 1e-10f) + 1e-10f);

    {
        float s = 0.f;
#pragma unroll
        for (int c = 0; c < KSPLIT; c++) s += g_simpart[c][b * P + t];
        sval[t] = s;
    }
    __syncthreads();

    for (int i = 0; i < TOPK; i++) {
        float bv = sval[t] + gn[i];
        int   bi = t;
#pragma unroll
        for (int o = 16; o > 0; o >>= 1) {
            float ov = __shfl_down_sync(0xffffffffu, bv, o);
            int   oi = __shfl_down_sync(0xffffffffu, bi, o);
            if (ov > bv || (ov == bv && oi < bi)) { bv = ov; bi = oi; }
        }
        if ((t & 31) == 0) { rv[t >> 5] = bv; ri[t >> 5] = bi; }
        __syncthreads();
        if (t == 0) {
            float fv = rv[0]; int fi = ri[0];
#pragma unroll
            for (int w = 1; w < 16; w++) {
                if (rv[w] > fv || (rv[w] == fv && ri[w] < fi)) { fv = rv[w]; fi = ri[w]; }
            }
            sidx[i] = fi;
            sval[fi] -= 1000.0f;   // training-mode mask-out (w == hard numerically)
        }
        __syncthreads();
    }

    // bulk copy: out[b, i*L:(i+1)*L, :] = prompt[sidx[i]]
    // 8192 float4 per block, 16 per thread: 4 chunks of (load 4, store 4).
    float4* dst = (float4*)out + (size_t)b * (TOPK * L * D / 4);
#pragma unroll
    for (int c = 0; c < 4; c++) {
        float4 r[4];
#pragma unroll
        for (int j = 0; j < 4; j++) {
            int vv  = c * 2048 + j * 512 + t;
            int i   = vv >> 11;            // 2048 float4 per selection
            int off = vv & 2047;
            r[j] = ((const float4*)prompt)[(size_t)sidx[i] * 2048 + off];
        }
#pragma unroll
        for (int j = 0; j < 4; j++) {
            int vv = c * 2048 + j * 512 + t;
            __stcs(&dst[vv], r[j]);
        }
    }
}

// ---------------------------------------------------------------------------
extern "C" void kernel_launch(void* const* d_in, const int* in_sizes, int n_in,
                              void* d_out, int out_size) {
    const float* x_embed    = (const float*)d_in[0];
    const float* prompt     = (const float*)d_in[1];
    const float* prompt_key = (const float*)d_in[2];
    const float* gumbel_u   = (const float*)d_in[3];
    float* out = (float*)d_out;

    const int gemm_smem = 2 * KCH * PITCH * (int)sizeof(float);  // 67584 B
    cudaFuncSetAttribute(k_sim_gemm, cudaFuncAttributeMaxDynamicSharedMemorySize,
                         gemm_smem);

    k_prep         <<<B + P / 4, 1024>>>(x_embed, prompt_key);
    k_sim_gemm     <<<dim3(B / 128, P / 128, KSPLIT), 256, gemm_smem>>>();
    k_select_gather<<<B, 512>>>(gumbel_u, prompt, out);
}